// round 5
// baseline (speedup 1.0000x reference)
#include <cuda_runtime.h>
#include <math.h>

#define NUM_TOKENS 16384
#define D_MODEL    2048
#define NUM_EXP    8
#define D4         (D_MODEL / 4)        // 512 float4 per token row
#define THREADS    512
#define WARPS      16
#define TOK_PER_WARP 8
#define TOK_PER_CTA  (WARPS * TOK_PER_WARP)   // 128
#define NUM_CTAS     (NUM_TOKENS / TOK_PER_CTA) // 128
#define KCHUNK_F4  32                   // float4 columns per chunk
#define KCHUNKS    (D4 / KCHUNK_F4)     // 16
#define NBUF       2
#define CHUNK_F4   (TOK_PER_WARP * KCHUNK_F4)   // 256 float4 = 4 KB

// ---- Blackwell packed fp32x2 helpers ----
__device__ __forceinline__ void fma2(unsigned long long& d,
                                     unsigned long long a,
                                     unsigned long long b)
{
    asm("fma.rn.f32x2 %0, %1, %2, %0;" : "+l"(d) : "l"(a), "l"(b));
}
__device__ __forceinline__ unsigned long long add2(unsigned long long a,
                                                   unsigned long long b)
{
    unsigned long long r;
    asm("add.rn.f32x2 %0, %1, %2;" : "=l"(r) : "l"(a), "l"(b));
    return r;
}
__device__ __forceinline__ unsigned long long bcast2(float v)
{
    unsigned long long r;
    asm("mov.b64 %0, {%1, %1};" : "=l"(r) : "f"(v));
    return r;
}
__device__ __forceinline__ float2 unpack2(unsigned long long v)
{
    float2 f;
    asm("mov.b64 {%0, %1}, %2;" : "=f"(f.x), "=f"(f.y) : "l"(v));
    return f;
}
__device__ __forceinline__ void cp_async16(void* smem_dst, const void* gmem_src)
{
    unsigned s = (unsigned)__cvta_generic_to_shared(smem_dst);
    asm volatile("cp.async.cg.shared.global [%0], [%1], 16;\n"
                 :: "r"(s), "l"(gmem_src));
}

// smem: sWlo[4ep*512] f4 (32KB) | sWhi[4ep*512] f4 (32KB) | xbuf[16w*2*256] f4 (128KB)
extern __shared__ float4 sm4[];
#define SW_LO 0
#define SW_HI (4 * D4)
#define XBUF  (8 * D4)

__global__ __launch_bounds__(THREADS, 1)
void gate_kernel(const float* __restrict__ x,
                 const float* __restrict__ W,
                 float* __restrict__ out,
                 int write_experts)
{
    const int tid  = threadIdx.x;
    const int warp = tid >> 5;
    const int lane = tid & 31;
    const int tok0 = blockIdx.x * TOK_PER_CTA + warp * TOK_PER_WARP;

    const float4* x4 = reinterpret_cast<const float4*>(x);
    // per-warp private double buffer
    float4* mybuf = sm4 + XBUF + warp * (NBUF * CHUNK_F4);
    const float4* gx = x4 + (size_t)tok0 * D4 + lane;   // lane's column base

    // ---- kick off chunk 0 BEFORE the W barrier (overlap) ----
    {
        #pragma unroll
        for (int t = 0; t < TOK_PER_WARP; t++)
            cp_async16(mybuf + t * KCHUNK_F4 + lane, gx + (size_t)t * D4);
        asm volatile("cp.async.commit_group;\n" ::: "memory");
    }

    // ---- Stage W as expert-pair interleaved f32x2, split lo/hi (64 KB) ----
    // entry (ep, c): lo = (W[2ep][4c],W[2ep+1][4c], W[2ep][4c+1],W[2ep+1][4c+1])
    //               hi = same for d = 4c+2, 4c+3
    for (int i = tid; i < 4 * D4; i += THREADS) {
        int ep = i >> 9, c = i & 511;
        const float* w0 = W + (2 * ep)     * D_MODEL + 4 * c;
        const float* w1 = W + (2 * ep + 1) * D_MODEL + 4 * c;
        sm4[SW_LO + i] = make_float4(w0[0], w1[0], w0[1], w1[1]);
        sm4[SW_HI + i] = make_float4(w0[2], w1[2], w0[3], w1[3]);
    }
    __syncthreads();   // the ONLY block barrier

    const ulonglong2* wlo = reinterpret_cast<const ulonglong2*>(sm4 + SW_LO);
    const ulonglong2* whi = reinterpret_cast<const ulonglong2*>(sm4 + SW_HI);

    unsigned long long acc[4][TOK_PER_WARP];   // f32x2 per (expert-pair, token)
    #pragma unroll
    for (int p = 0; p < 4; p++)
        #pragma unroll
        for (int t = 0; t < TOK_PER_WARP; t++)
            acc[p][t] = 0ull;

    // ---- barrier-free per-warp pipeline over 16 K-chunks ----
    #pragma unroll 2
    for (int kc = 0; kc < KCHUNKS; kc++) {
        // stage chunk kc+1 into the other buffer (commit even when empty
        // to keep group arithmetic uniform)
        if (kc + 1 < KCHUNKS) {
            float4* dst = mybuf + ((kc + 1) & 1) * CHUNK_F4;
            const float4* src = gx + (size_t)(kc + 1) * KCHUNK_F4;
            #pragma unroll
            for (int t = 0; t < TOK_PER_WARP; t++)
                cp_async16(dst + t * KCHUNK_F4 + lane, src + (size_t)t * D4);
        }
        asm volatile("cp.async.commit_group;\n" ::: "memory");
        asm volatile("cp.async.wait_group 1;\n" ::: "memory");  // chunk kc ready

        // W cache for this chunk: lane's f4 column, 4 expert pairs, lo+hi
        const int c = kc * KCHUNK_F4 + lane;
        ulonglong2 WL[4], WH[4];
        #pragma unroll
        for (int p = 0; p < 4; p++) {
            WL[p] = wlo[p * D4 + c];
            WH[p] = whi[p * D4 + c];
        }

        const float4* xb = mybuf + (kc & 1) * CHUNK_F4 + lane;
        #pragma unroll
        for (int t = 0; t < TOK_PER_WARP; t++) {
            float4 xv = xb[t * KCHUNK_F4];
            unsigned long long x0 = bcast2(xv.x), x1 = bcast2(xv.y);
            unsigned long long x2 = bcast2(xv.z), x3 = bcast2(xv.w);
            #pragma unroll
            for (int p = 0; p < 4; p++) {
                fma2(acc[p][t], x0, WL[p].x);
                fma2(acc[p][t], x1, WL[p].y);
                fma2(acc[p][t], x2, WH[p].x);
                fma2(acc[p][t], x3, WH[p].y);
            }
        }
    }

    // ---- warp butterfly reduction on packed accumulators ----
    #pragma unroll
    for (int off = 16; off >= 1; off >>= 1)
        #pragma unroll
        for (int p = 0; p < 4; p++)
            #pragma unroll
            for (int t = 0; t < TOK_PER_WARP; t++)
                acc[p][t] = add2(acc[p][t],
                                 __shfl_xor_sync(0xFFFFFFFFu, acc[p][t], off));

    // lane t (<8) finalizes token tok0 + t
    float logit[NUM_EXP];
    #pragma unroll
    for (int p = 0; p < 4; p++) {
        unsigned long long v = acc[p][0];
        #pragma unroll
        for (int t = 1; t < TOK_PER_WARP; t++)
            v = (lane == t) ? acc[p][t] : v;
        float2 f = unpack2(v);
        logit[2 * p]     = f.x;
        logit[2 * p + 1] = f.y;
    }

    if (lane < TOK_PER_WARP) {
        const int tok = tok0 + lane;

        // top-2 scan; strict '>' keeps lowest index on ties (JAX top_k)
        float v1 = logit[0], v2 = -INFINITY;
        int   i1 = 0,        i2 = 0;
        #pragma unroll
        for (int e = 1; e < NUM_EXP; e++) {
            float le = logit[e];
            if (le > v1)      { v2 = v1; i2 = i1; v1 = le; i1 = e; }
            else if (le > v2) { v2 = le; i2 = e; }
        }

        // softmax + top-2 + renorm == 2-way softmax over top-2 logits
        float r  = __expf(v2 - v1);
        float w1 = 1.0f / (1.0f + r);
        float w2 = 1.0f - w1;

        out[tok * 2 + 0] = w1;
        out[tok * 2 + 1] = w2;
        if (write_experts) {
            out[2 * NUM_TOKENS + tok * 2 + 0] = (float)i1;
            out[2 * NUM_TOKENS + tok * 2 + 1] = (float)i2;
        }
    }
}

extern "C" void kernel_launch(void* const* d_in, const int* in_sizes, int n_in,
                              void* d_out, int out_size)
{
    const float* x = (const float*)d_in[0];
    const float* W = (const float*)d_in[1];
    float* out = (float*)d_out;

    int write_experts = (out_size >= 4 * NUM_TOKENS) ? 1 : 0;

    const int smem = (8 * D4 + WARPS * NBUF * CHUNK_F4) * (int)sizeof(float4); // 192 KB
    cudaFuncSetAttribute(gate_kernel, cudaFuncAttributeMaxDynamicSharedMemorySize, smem);

    gate_kernel<<<NUM_CTAS, THREADS, smem>>>(x, W, out, write_experts);
}

// round 6
// speedup vs baseline: 1.0676x; 1.0676x over previous
#include <cuda_runtime.h>
#include <math.h>

#define NUM_TOKENS 16384
#define D_MODEL    2048
#define NUM_EXP    8
#define D4         512                 // float4 per token row
#define HALF_F4    256                 // float4 per d-half
#define THREADS    256
#define WARPS      8
#define TOK_PER_WARP 4
#define TOK_PER_CTA  32                // 8 warps * 4 tokens
#define ITERS      8                   // HALF_F4 / 32 lanes
#define NUM_CTAS   (2 * NUM_TOKENS / TOK_PER_CTA)   // 1024 (x2 for the 2 halves)

// ---- Blackwell packed fp32x2 helpers ----
__device__ __forceinline__ void fma2(unsigned long long& d,
                                     unsigned long long a,
                                     unsigned long long b)
{
    asm("fma.rn.f32x2 %0, %1, %2, %0;" : "+l"(d) : "l"(a), "l"(b));
}
__device__ __forceinline__ unsigned long long add2(unsigned long long a,
                                                   unsigned long long b)
{
    unsigned long long r;
    asm("add.rn.f32x2 %0, %1, %2;" : "=l"(r) : "l"(a), "l"(b));
    return r;
}
__device__ __forceinline__ unsigned long long bcast2(float v)
{
    unsigned long long r;
    asm("mov.b64 %0, {%1, %1};" : "=l"(r) : "f"(v));
    return r;
}
__device__ __forceinline__ float2 unpack2(unsigned long long v)
{
    float2 f;
    asm("mov.b64 {%0, %1}, %2;" : "=f"(f.x), "=f"(f.y) : "l"(v));
    return f;
}

// Partial logits scratch: [half][token][expert], written by gemm, read by topk.
__device__ float g_part[2 * NUM_TOKENS * NUM_EXP];

// smem: sWlo[4ep * 256c] f4 (16KB) | sWhi[...] f4 (16KB)  = 32 KB
extern __shared__ float4 sm4[];
#define SW_LO 0
#define SW_HI (4 * HALF_F4)

__global__ __launch_bounds__(THREADS, 4)
void gemm_kernel(const float* __restrict__ x,
                 const float* __restrict__ W)
{
    const int tid  = threadIdx.x;
    const int warp = tid >> 5;
    const int lane = tid & 31;
    const int h    = blockIdx.x & 1;                      // d-half
    const int tok0 = (blockIdx.x >> 1) * TOK_PER_CTA + warp * TOK_PER_WARP;

    // ---- Stage this half of W, expert-pair interleaved, lo/hi split ----
    // entry (ep, c): covers global d = h*1024 + 4c .. +3 for experts 2ep, 2ep+1
    //   lo = (W[2ep][d], W[2ep+1][d], W[2ep][d+1], W[2ep+1][d+1])
    //   hi = same for d+2, d+3
    for (int i = tid; i < 4 * HALF_F4; i += THREADS) {
        const int ep = i >> 8;          // 0..3
        const int c  = i & 255;
        const float* w0 = W + (2 * ep)     * D_MODEL + h * 1024 + 4 * c;
        const float* w1 = W + (2 * ep + 1) * D_MODEL + h * 1024 + 4 * c;
        sm4[SW_LO + i] = make_float4(w0[0], w1[0], w0[1], w1[1]);
        sm4[SW_HI + i] = make_float4(w0[2], w1[2], w0[3], w1[3]);
    }
    __syncthreads();

    const ulonglong2* wlo = reinterpret_cast<const ulonglong2*>(sm4 + SW_LO);
    const ulonglong2* whi = reinterpret_cast<const ulonglong2*>(sm4 + SW_HI);

    // lane's float4 column base for this half
    const float4* gx = reinterpret_cast<const float4*>(x)
                     + (size_t)tok0 * D4 + h * HALF_F4 + lane;

    unsigned long long acc[4][TOK_PER_WARP];   // f32x2 per (expert-pair, token)
    #pragma unroll
    for (int p = 0; p < 4; p++)
        #pragma unroll
        for (int t = 0; t < TOK_PER_WARP; t++)
            acc[p][t] = 0ull;

    #pragma unroll 2
    for (int it = 0; it < ITERS; it++) {
        // 4 independent LDG.128 (one per token) — MLP_p1 = 4
        float4 xv[TOK_PER_WARP];
        #pragma unroll
        for (int t = 0; t < TOK_PER_WARP; t++)
            xv[t] = gx[(size_t)t * D4 + it * 32];

        unsigned long long xb[TOK_PER_WARP][4];
        #pragma unroll
        for (int t = 0; t < TOK_PER_WARP; t++) {
            xb[t][0] = bcast2(xv[t].x);
            xb[t][1] = bcast2(xv[t].y);
            xb[t][2] = bcast2(xv[t].z);
            xb[t][3] = bcast2(xv[t].w);
        }

        const int c = it * 32 + lane;
        #pragma unroll
        for (int p = 0; p < 4; p++) {
            ulonglong2 WL = wlo[p * HALF_F4 + c];
            ulonglong2 WH = whi[p * HALF_F4 + c];
            #pragma unroll
            for (int t = 0; t < TOK_PER_WARP; t++) {
                fma2(acc[p][t], xb[t][0], WL.x);
                fma2(acc[p][t], xb[t][1], WL.y);
                fma2(acc[p][t], xb[t][2], WH.x);
                fma2(acc[p][t], xb[t][3], WH.y);
            }
        }
    }

    // ---- warp butterfly reduction on packed accumulators ----
    #pragma unroll
    for (int off = 16; off >= 1; off >>= 1)
        #pragma unroll
        for (int p = 0; p < 4; p++)
            #pragma unroll
            for (int t = 0; t < TOK_PER_WARP; t++)
                acc[p][t] = add2(acc[p][t],
                                 __shfl_xor_sync(0xFFFFFFFFu, acc[p][t], off));

    // lane t (<4) owns token tok0 + t: assemble 8 partial logits, store 32 B
    float logit[NUM_EXP];
    #pragma unroll
    for (int p = 0; p < 4; p++) {
        unsigned long long v = acc[p][0];
        #pragma unroll
        for (int t = 1; t < TOK_PER_WARP; t++)
            v = (lane == t) ? acc[p][t] : v;
        float2 f = unpack2(v);
        logit[2 * p]     = f.x;
        logit[2 * p + 1] = f.y;
    }

    if (lane < TOK_PER_WARP) {
        const int tok = tok0 + lane;
        float4* dst = reinterpret_cast<float4*>(g_part)
                    + ((size_t)h * NUM_TOKENS + tok) * 2;
        dst[0] = make_float4(logit[0], logit[1], logit[2], logit[3]);
        dst[1] = make_float4(logit[4], logit[5], logit[6], logit[7]);
    }
}

__global__ __launch_bounds__(256)
void topk_kernel(float* __restrict__ out, int write_experts)
{
    const int tok = blockIdx.x * 256 + threadIdx.x;

    const float4* p0 = reinterpret_cast<const float4*>(g_part) + (size_t)tok * 2;
    const float4* p1 = p0 + (size_t)NUM_TOKENS * 2;
    float4 a0 = p0[0], a1 = p0[1];
    float4 b0 = p1[0], b1 = p1[1];

    float logit[NUM_EXP] = {
        a0.x + b0.x, a0.y + b0.y, a0.z + b0.z, a0.w + b0.w,
        a1.x + b1.x, a1.y + b1.y, a1.z + b1.z, a1.w + b1.w
    };

    // top-2 scan; strict '>' keeps lowest index on ties (JAX top_k)
    float v1 = logit[0], v2 = -INFINITY;
    int   i1 = 0,        i2 = 0;
    #pragma unroll
    for (int e = 1; e < NUM_EXP; e++) {
        float le = logit[e];
        if (le > v1)      { v2 = v1; i2 = i1; v1 = le; i1 = e; }
        else if (le > v2) { v2 = le; i2 = e; }
    }

    // softmax + top-2 + renorm == 2-way softmax over the top-2 logits
    float r  = __expf(v2 - v1);
    float w1 = 1.0f / (1.0f + r);
    float w2 = 1.0f - w1;

    out[tok * 2 + 0] = w1;
    out[tok * 2 + 1] = w2;
    if (write_experts) {
        out[2 * NUM_TOKENS + tok * 2 + 0] = (float)i1;
        out[2 * NUM_TOKENS + tok * 2 + 1] = (float)i2;
    }
}

extern "C" void kernel_launch(void* const* d_in, const int* in_sizes, int n_in,
                              void* d_out, int out_size)
{
    const float* x = (const float*)d_in[0];
    const float* W = (const float*)d_in[1];
    float* out = (float*)d_out;

    int write_experts = (out_size >= 4 * NUM_TOKENS) ? 1 : 0;

    const int smem = 8 * HALF_F4 * (int)sizeof(float4);   // 32 KB
    cudaFuncSetAttribute(gemm_kernel, cudaFuncAttributeMaxDynamicSharedMemorySize, smem);

    gemm_kernel<<<NUM_CTAS, THREADS, smem>>>(x, W);
    topk_kernel<<<NUM_TOKENS / 256, 256>>>(out, write_experts);
}

// round 8
// speedup vs baseline: 1.1899x; 1.1145x over previous
#include <cuda_runtime.h>
#include <math.h>

#define NUM_TOKENS 16384
#define D_MODEL    2048
#define NUM_EXP    8
#define D4         512                    // float4 per token row
#define THREADS    256
#define WARPS      8
#define TOK_PER_WARP 8
#define TOK_PER_CTA  64                   // 8 warps * 8 tokens
#define NUM_CTAS   (NUM_TOKENS / TOK_PER_CTA)   // 256
#define NCHUNKS    8                      // d split: 256 floats per chunk
#define CHUNK_FLOATS 256
#define CHUNK_BYTES_ROW 1024              // per token row per chunk
#define CHUNK_BYTES (TOK_PER_WARP * CHUNK_BYTES_ROW)  // 8 KB
#define NBUF       2

// ---- Blackwell packed fp32x2 helpers ----
__device__ __forceinline__ void fma2(unsigned long long& d,
                                     unsigned long long a,
                                     unsigned long long b)
{
    asm("fma.rn.f32x2 %0, %1, %2, %0;" : "+l"(d) : "l"(a), "l"(b));
}
__device__ __forceinline__ unsigned long long add2(unsigned long long a,
                                                   unsigned long long b)
{
    unsigned long long r;
    asm("add.rn.f32x2 %0, %1, %2;" : "=l"(r) : "l"(a), "l"(b));
    return r;
}
__device__ __forceinline__ unsigned long long bcast2(float v)
{
    unsigned long long r;
    asm("mov.b64 %0, {%1, %1};" : "=l"(r) : "f"(v));
    return r;
}
__device__ __forceinline__ float2 unpack2(unsigned long long v)
{
    float2 f;
    asm("mov.b64 {%0, %1}, %2;" : "=f"(f.x), "=f"(f.y) : "l"(v));
    return f;
}

// ---- mbarrier / bulk-copy primitives ----
__device__ __forceinline__ void mbar_init(unsigned mbar, unsigned count)
{
    asm volatile("mbarrier.init.shared.b64 [%0], %1;" :: "r"(mbar), "r"(count) : "memory");
}
__device__ __forceinline__ void mbar_expect_tx(unsigned mbar, unsigned bytes)
{
    asm volatile("mbarrier.arrive.expect_tx.shared.b64 _, [%0], %1;"
                 :: "r"(mbar), "r"(bytes) : "memory");
}
__device__ __forceinline__ void mbar_wait(unsigned mbar, unsigned phase)
{
    unsigned done;
    asm volatile(
        "{\n\t.reg .pred p;\n\t"
        "mbarrier.try_wait.parity.acquire.cta.shared::cta.b64 p, [%1], %2;\n\t"
        "selp.b32 %0, 1, 0, p;\n\t}"
        : "=r"(done) : "r"(mbar), "r"(phase) : "memory");
    if (!done) {
        asm volatile(
            "{\n\t.reg .pred P1;\n\t"
            "W_%=:\n\t"
            "mbarrier.try_wait.parity.acquire.cta.shared::cta.b64 P1, [%0], %1, 0x989680;\n\t"
            "@P1 bra.uni D_%=;\n\t"
            "bra.uni W_%=;\n\t"
            "D_%=:\n\t}"
            :: "r"(mbar), "r"(phase) : "memory");
    }
}
__device__ __forceinline__ void bulk_cp(unsigned smem_dst, const void* gmem_src,
                                        unsigned bytes, unsigned mbar)
{
    asm volatile(
        "cp.async.bulk.shared::cta.global.mbarrier::complete_tx::bytes [%0], [%1], %2, [%3];"
        :: "r"(smem_dst), "l"(gmem_src), "r"(bytes), "r"(mbar) : "memory");
}

// smem layout (bytes):
//   [0, 128)            mbars: warp w, buf b at w*16 + b*8
//   [1024, 66560)       W expert-pair interleaved: lo 32 KB | hi 32 KB
//   [66560, 197632)     x buffers: warp w, buf b -> 8 KB each
#define SM_MBAR  0
#define SM_W     1024
#define SM_XBUF  66560

extern __shared__ char smem[];

__global__ __launch_bounds__(THREADS, 1)
void gate_kernel(const float* __restrict__ x,
                 const float* __restrict__ W,
                 float* __restrict__ out,
                 int write_experts)
{
    const int tid  = threadIdx.x;
    const int warp = tid >> 5;
    const int lane = tid & 31;
    const int tok0 = blockIdx.x * TOK_PER_CTA + warp * TOK_PER_WARP;

    const unsigned smem_base = (unsigned)__cvta_generic_to_shared(smem);
    const unsigned my_mbar0  = smem_base + SM_MBAR + warp * 16;
    const unsigned my_xbuf   = smem_base + SM_XBUF + warp * (NBUF * CHUNK_BYTES);

    // per-warp mbarrier init (lane 0); visible to all after __syncthreads below
    if (lane == 0) {
        mbar_init(my_mbar0,     1);
        mbar_init(my_mbar0 + 8, 1);
    }

    // ---- Stage W: expert-pair interleaved f32x2, lo/hi split (64 KB) ----
    // (ep, c): lo = (W[2ep][4c],W[2ep+1][4c], W[2ep][4c+1],W[2ep+1][4c+1]); hi = d+2,d+3
    {
        float4* sW = reinterpret_cast<float4*>(smem + SM_W);
        for (int i = tid; i < 4 * D4; i += THREADS) {
            const int ep = i >> 9, c = i & 511;
            const float* w0 = W + (2 * ep)     * D_MODEL + 4 * c;
            const float* w1 = W + (2 * ep + 1) * D_MODEL + 4 * c;
            sW[i]          = make_float4(w0[0], w1[0], w0[1], w1[1]);
            sW[i + 4 * D4] = make_float4(w0[2], w1[2], w0[3], w1[3]);
        }
    }
    __syncthreads();    // W + mbarrier init visible; only block barrier

    const float* gx = x + (size_t)tok0 * D_MODEL;

    // stage chunk kc into buffer b (lane 0 only): 8 rows x 1 KB bulk copies
    auto stage = [&](int kc, int b) {
        const unsigned mb  = my_mbar0 + b * 8;
        const unsigned dst = my_xbuf + b * CHUNK_BYTES;
        mbar_expect_tx(mb, CHUNK_BYTES);
        #pragma unroll
        for (int r = 0; r < TOK_PER_WARP; r++)
            bulk_cp(dst + r * CHUNK_BYTES_ROW,
                    gx + (size_t)r * D_MODEL + kc * CHUNK_FLOATS,
                    CHUNK_BYTES_ROW, mb);
    };

    if (lane == 0) stage(0, 0);

    const ulonglong2* wlo = reinterpret_cast<const ulonglong2*>(smem + SM_W);
    const ulonglong2* whi = wlo + 4 * D4;   // FIX: hi half starts 32 KB (= 4*D4 x 16B) in

    unsigned long long acc[4][TOK_PER_WARP];    // f32x2 per (expert-pair, token)
    #pragma unroll
    for (int p = 0; p < 4; p++)
        #pragma unroll
        for (int t = 0; t < TOK_PER_WARP; t++)
            acc[p][t] = 0ull;

    for (int kc = 0; kc < NCHUNKS; kc++) {
        const int b = kc & 1;
        // issue next chunk into the other buffer (its previous contents were
        // consumed at chunk kc-1; warp program order makes reuse safe)
        if (lane == 0 && kc + 1 < NCHUNKS) stage(kc + 1, b ^ 1);

        mbar_wait(my_mbar0 + b * 8, (kc >> 1) & 1);

        const float4* xb = reinterpret_cast<const float4*>(
            smem + SM_XBUF + (warp * NBUF + b) * CHUNK_BYTES);

        #pragma unroll
        for (int i = 0; i < 2; i++) {           // 64 f4 cols / 32 lanes
            const int c = kc * 64 + i * 32 + lane;   // global f4 column
            ulonglong2 WL[4], WH[4];
            #pragma unroll
            for (int p = 0; p < 4; p++) {
                WL[p] = wlo[p * D4 + c];
                WH[p] = whi[p * D4 + c];
            }
            #pragma unroll
            for (int t = 0; t < TOK_PER_WARP; t++) {
                // row t, f4 col (i*32+lane) within this 64-f4-wide chunk row
                float4 xv = xb[t * 64 + i * 32 + lane];
                unsigned long long x0 = bcast2(xv.x), x1 = bcast2(xv.y);
                unsigned long long x2 = bcast2(xv.z), x3 = bcast2(xv.w);
                #pragma unroll
                for (int p = 0; p < 4; p++) {
                    fma2(acc[p][t], x0, WL[p].x);
                    fma2(acc[p][t], x1, WL[p].y);
                    fma2(acc[p][t], x2, WH[p].x);
                    fma2(acc[p][t], x3, WH[p].y);
                }
            }
        }
    }

    // ---- warp butterfly reduction on packed accumulators ----
    #pragma unroll
    for (int off = 16; off >= 1; off >>= 1)
        #pragma unroll
        for (int p = 0; p < 4; p++)
            #pragma unroll
            for (int t = 0; t < TOK_PER_WARP; t++)
                acc[p][t] = add2(acc[p][t],
                                 __shfl_xor_sync(0xFFFFFFFFu, acc[p][t], off));

    // lane t (<8) finalizes token tok0 + t
    float logit[NUM_EXP];
    #pragma unroll
    for (int p = 0; p < 4; p++) {
        unsigned long long v = acc[p][0];
        #pragma unroll
        for (int t = 1; t < TOK_PER_WARP; t++)
            v = (lane == t) ? acc[p][t] : v;
        float2 f = unpack2(v);
        logit[2 * p]     = f.x;
        logit[2 * p + 1] = f.y;
    }

    if (lane < TOK_PER_WARP) {
        const int tok = tok0 + lane;

        // top-2 scan; strict '>' keeps lowest index on ties (JAX top_k)
        float v1 = logit[0], v2 = -INFINITY;
        int   i1 = 0,        i2 = 0;
        #pragma unroll
        for (int e = 1; e < NUM_EXP; e++) {
            float le = logit[e];
            if (le > v1)      { v2 = v1; i2 = i1; v1 = le; i1 = e; }
            else if (le > v2) { v2 = le; i2 = e; }
        }

        // softmax + top-2 + renorm == 2-way softmax over top-2 logits
        float r  = __expf(v2 - v1);
        float w1 = 1.0f / (1.0f + r);
        float w2 = 1.0f - w1;

        out[tok * 2 + 0] = w1;
        out[tok * 2 + 1] = w2;
        if (write_experts) {
            out[2 * NUM_TOKENS + tok * 2 + 0] = (float)i1;
            out[2 * NUM_TOKENS + tok * 2 + 1] = (float)i2;
        }
    }
}

extern "C" void kernel_launch(void* const* d_in, const int* in_sizes, int n_in,
                              void* d_out, int out_size)
{
    const float* x = (const float*)d_in[0];
    const float* W = (const float*)d_in[1];
    float* out = (float*)d_out;

    int write_experts = (out_size >= 4 * NUM_TOKENS) ? 1 : 0;

    const int smem = SM_XBUF + WARPS * NBUF * CHUNK_BYTES;   // 66560 + 131072 = 197632
    cudaFuncSetAttribute(gate_kernel, cudaFuncAttributeMaxDynamicSharedMemorySize, smem);

    gate_kernel<<<NUM_CTAS, THREADS, smem>>>(x, W, out, write_experts);
}